// round 1
// baseline (speedup 1.0000x reference)
#include <cuda_runtime.h>

// Nearest-neighbor 2x upsample, NHWC fp32.
// In : x (8, 128, 128, 256)  -> 8*128*128*256 floats = 128 MiB
// Out:   (8, 256, 256, 256)  -> 512 MiB
// Input-centric: each thread loads one float4 of the input and stores it to
// the 4 (2x2) replicated output positions. Input read exactly once.
//
// Fixed shapes (from reference setup_inputs): B=8, H=W=128, C=256, factor=2.
// C4 = C/4 = 64 float4 per pixel. All power-of-two -> shift/mask indexing.

__global__ __launch_bounds__(256) void upsample2x_kernel(
    const float4* __restrict__ in, float4* __restrict__ out)
{
    const int idx = blockIdx.x * blockDim.x + threadIdx.x;   // 0 .. 8388607
    // Decompose input float4 index: ((b*128 + h)*128 + w)*64 + c4
    const int c4 = idx & 63;
    const int w  = (idx >> 6) & 127;
    const int h  = (idx >> 13) & 127;
    const int b  = idx >> 20;

    const float4 v = in[idx];

    // Output float4 index: ((b*256 + 2h+dh)*256 + 2w+dw)*64 + c4
    //  b stride : 256*256*64 = 1<<22
    //  2h stride: 2*256*64   = h<<15 (dh adds 1<<14)
    //  2w stride: 2*64       = w<<7  (dw adds 64)
    const int o = (b << 22) + (h << 15) + (w << 7) + c4;

    out[o]                 = v;   // (2h,   2w)
    out[o + 64]            = v;   // (2h,   2w+1)
    out[o + (1 << 14)]     = v;   // (2h+1, 2w)
    out[o + (1 << 14) + 64] = v;  // (2h+1, 2w+1)
}

extern "C" void kernel_launch(void* const* d_in, const int* in_sizes, int n_in,
                              void* d_out, int out_size)
{
    const float4* in  = (const float4*)d_in[0];
    float4*       out = (float4*)d_out;

    // 8*128*128*256 floats / 4 = 8388608 float4 elements
    const int n4 = 8 * 128 * 128 * 64;
    const int threads = 256;
    const int blocks  = n4 / threads;  // 32768

    upsample2x_kernel<<<blocks, threads>>>(in, out);
}